// round 16
// baseline (speedup 1.0000x reference)
#include <cuda_runtime.h>
#include <cstdint>

// MultiScaleDeformableAttention — smem-cached coarse levels + deep gather pipeline.
//
// value:              (8, 22223, 8, 32)  float32
// sampling_locations: (8, 900, 8, 4, 4, 2) float32
// attention_weights:  (8, 900, 8, 4, 4) float32
// out:                (8, 900, 256) float32
//
// Grid re-blocked as (b, h, query-chunk): 960 blocks x 480 threads,
// each block = one (b,h) and 60 queries (60 tuples x 8 c4-lanes).
//
// Levels 2+3 (1050 + 273 = 1323 keys) for a fixed (b,h) are only 165 KB:
// preloaded to shared memory once per block (slice is L2-resident across the
// 15 blocks sharing it). Points 8..15 are then served by conflict-free
// LDS.128 instead of global gathers -> global miss stream halved.
//
// Levels 0+1 (points 0..7) use the proven register-resident pipeline,
// deepened to 3-ahead (4 slots) with the register headroom of 1 CTA/SM.

#define NQ 900
#define NH 8
#define ND 32
#define BS 8
#define NKEYS 22223
#define QB 60                       // queries (tuples) per block
#define THREADS (QB * 8)            // 480
#define NBLOCKS (BS * NH * (NQ / QB))  // 8*8*15 = 960

#define L23_KEY0 20900              // first key of level 2
#define L23_KEYS 1323               // level2 (1050) + level3 (273)
#define SLICE_FLOATS (L23_KEYS * 32)   // 42336 floats = 169,344 B

// smem layout:
//   [0, SLICE_FLOATS) floats         value slice (levels 2+3)
//   s_off: 16 points x 60 tuples int4   (15,360 B)
//   s_wt : 16 points x 60 tuples float4 (15,360 B)
#define SMEM_BYTES (SLICE_FLOATS * 4 + 16 * QB * 16 * 2)   // 200,064

__device__ __forceinline__ void point_setup(
    float lx, float ly, float w,
    int H, int W, int S, int stride,
    int& o00, int& o10, int& o01, int& o11,
    float& w00, float& w10, float& w01, float& w11)
{
    const float x = lx * (float)W - 0.5f;
    const float y = ly * (float)H - 0.5f;
    const float x0f = floorf(x);
    const float y0f = floorf(y);
    const int x0 = (int)x0f;
    const int y0 = (int)y0f;
    const int x1 = x0 + 1;
    const int y1 = y0 + 1;
    const float fx1 = x - x0f;
    const float fy1 = y - y0f;
    const float fx0 = 1.0f - fx1;
    const float fy0 = 1.0f - fy1;

    // zero weight factor for OOB corners; fold aw into the y factors.
    const float mx0 = (x0 >= 0 && x0 < W) ? fx0 : 0.0f;
    const float mx1 = (x1 >= 0 && x1 < W) ? fx1 : 0.0f;
    const float my0 = (y0 >= 0 && y0 < H) ? fy0 * w : 0.0f;
    const float my1 = (y1 >= 0 && y1 < H) ? fy1 * w : 0.0f;

    const int cx0 = min(max(x0, 0), W - 1);
    const int cx1 = min(max(x1, 0), W - 1);
    const int cy0 = min(max(y0, 0), H - 1);
    const int cy1 = min(max(y1, 0), H - 1);

    const int r0 = S + cy0 * W;
    const int r1 = S + cy1 * W;

    o00 = (r0 + cx0) * stride;
    o10 = (r0 + cx1) * stride;
    o01 = (r1 + cx0) * stride;
    o11 = (r1 + cx1) * stride;

    w00 = mx0 * my0;
    w10 = mx1 * my0;
    w01 = mx0 * my1;
    w11 = mx1 * my1;
}

__global__ __launch_bounds__(THREADS, 1)
void msda_kernel(const float* __restrict__ value,
                 const float* __restrict__ loc,
                 const float* __restrict__ aw,
                 float* __restrict__ out)
{
    extern __shared__ float smem_f[];
    float* __restrict__ sval = smem_f;                         // 42336 floats
    int4*   __restrict__ s_off = (int4*)(smem_f + SLICE_FLOATS);
    float4* __restrict__ s_wt  = (float4*)((char*)s_off + 16 * QB * 16);

    const int tid = threadIdx.x;
    const int bid = blockIdx.x;

    // block -> (b, h, query chunk)
    const int qc = bid % 15;
    const int h  = (bid / 15) & 7;
    const int b  = bid / 120;
    const int q0 = qc * QB;

    // ---------------- preload level-2/3 value slice ----------------
    {
        // global float4 base for (b, key=L23_KEY0, h, 0)
        const float4* __restrict__ gsrc = (const float4*)
            (value + ((size_t)b * NKEYS + L23_KEY0) * (NH * ND) + h * ND);
        float4* __restrict__ dst = (float4*)sval;
        // row kl occupies global float4s [kl*64 + 0 .. 7] (stride 64 per key)
        #pragma unroll 4
        for (int i = tid; i < L23_KEYS * 8; i += THREADS) {
            const int kl  = i >> 3;
            const int c4p = i & 7;
            dst[i] = __ldg(gsrc + (size_t)kl * 64 + c4p);
        }
    }

    // ---------------- Phase A: per-tuple setup, computed once ----------------
    {
        const int tl   = tid >> 3;           // tuple_local 0..59
        const int pair = tid & 7;            // point-pair -> points 2p, 2p+1
        const int q    = q0 + tl;
        const int t    = (b * NQ + q) * NH + h;
        const int p0   = pair * 2;
        const int l    = p0 >> 2;            // both points share a level

        const int H = (l == 0) ? 100 : (l == 1) ? 50 : (l == 2) ? 25 : 13;
        const int W = (l == 0) ? 167 : (l == 1) ? 84 : (l == 2) ? 42 : 21;
        // levels 0/1: global key offset, stride 256 floats.
        // levels 2/3: slice-local key offset, stride 32 floats.
        const int S  = (l == 0) ? 0 : (l == 1) ? 16700 : (l == 2) ? 0 : 1050;
        const int VS = (l < 2) ? (NH * ND) : ND;

        const float4 lp = __ldg((const float4*)(loc + (size_t)t * 32) + pair);
        const float2 wp = __ldg((const float2*)(aw  + (size_t)t * 16) + pair);

        int   o00, o10, o01, o11;
        float w00, w10, w01, w11;

        point_setup(lp.x, lp.y, wp.x, H, W, S, VS,
                    o00, o10, o01, o11, w00, w10, w01, w11);
        s_off[p0 * QB + tl] = make_int4(o00, o10, o01, o11);
        s_wt [p0 * QB + tl] = make_float4(w00, w10, w01, w11);

        point_setup(lp.z, lp.w, wp.y, H, W, S, VS,
                    o00, o10, o01, o11, w00, w10, w01, w11);
        s_off[(p0 + 1) * QB + tl] = make_int4(o00, o10, o01, o11);
        s_wt [(p0 + 1) * QB + tl] = make_float4(w00, w10, w01, w11);
    }
    __syncthreads();

    // ---------------- Phase B ----------------
    const int tl = tid >> 3;
    const int c4 = tid & 7;
    const int q  = q0 + tl;
    const int t  = (b * NQ + q) * NH + h;

    const float* __restrict__ vbase =
        value + (size_t)b * (NKEYS * NH * ND) + h * ND + c4 * 4;
    const float* __restrict__ sbase = sval + c4 * 4;

    float4 acc0 = make_float4(0.f, 0.f, 0.f, 0.f);
    float4 acc1 = make_float4(0.f, 0.f, 0.f, 0.f);

    // -- points 0..7 (levels 0/1): 4-slot register pipeline, 3 points ahead --
    {
        float4 v00[4], v10[4], v01[4], v11[4];
        float4 wt[4];

        auto issue = [&](int pi, int s) {
            const int4 o = s_off[pi * QB + tl];
            wt[s]        = s_wt [pi * QB + tl];
            v00[s] = __ldg((const float4*)(vbase + o.x));
            v10[s] = __ldg((const float4*)(vbase + o.y));
            v01[s] = __ldg((const float4*)(vbase + o.z));
            v11[s] = __ldg((const float4*)(vbase + o.w));
        };

        issue(0, 0);
        issue(1, 1);
        issue(2, 2);

        #pragma unroll
        for (int pi = 0; pi < 8; ++pi) {
            const int cur = pi & 3;
            if (pi < 5)
                issue(pi + 3, (pi + 3) & 3);

            const float a = wt[cur].x, bw = wt[cur].y, c = wt[cur].z, d = wt[cur].w;
            const float4 p00 = v00[cur], p10 = v10[cur], p01 = v01[cur], p11 = v11[cur];
            float4& acc = (pi & 1) ? acc1 : acc0;

            acc.x = fmaf(a, p00.x, acc.x);
            acc.y = fmaf(a, p00.y, acc.y);
            acc.z = fmaf(a, p00.z, acc.z);
            acc.w = fmaf(a, p00.w, acc.w);

            acc.x = fmaf(bw, p10.x, acc.x);
            acc.y = fmaf(bw, p10.y, acc.y);
            acc.z = fmaf(bw, p10.z, acc.z);
            acc.w = fmaf(bw, p10.w, acc.w);

            acc.x = fmaf(c, p01.x, acc.x);
            acc.y = fmaf(c, p01.y, acc.y);
            acc.z = fmaf(c, p01.z, acc.z);
            acc.w = fmaf(c, p01.w, acc.w);

            acc.x = fmaf(d, p11.x, acc.x);
            acc.y = fmaf(d, p11.y, acc.y);
            acc.z = fmaf(d, p11.z, acc.z);
            acc.w = fmaf(d, p11.w, acc.w);
        }
    }

    // -- points 8..15 (levels 2/3): served from shared memory --
    #pragma unroll
    for (int pi = 8; pi < 16; ++pi) {
        const int4   o = s_off[pi * QB + tl];
        const float4 w = s_wt [pi * QB + tl];

        const float4 p00 = *(const float4*)(sbase + o.x);
        const float4 p10 = *(const float4*)(sbase + o.y);
        const float4 p01 = *(const float4*)(sbase + o.z);
        const float4 p11 = *(const float4*)(sbase + o.w);

        float4& acc = (pi & 1) ? acc1 : acc0;

        acc.x = fmaf(w.x, p00.x, acc.x);
        acc.y = fmaf(w.x, p00.y, acc.y);
        acc.z = fmaf(w.x, p00.z, acc.z);
        acc.w = fmaf(w.x, p00.w, acc.w);

        acc.x = fmaf(w.y, p10.x, acc.x);
        acc.y = fmaf(w.y, p10.y, acc.y);
        acc.z = fmaf(w.y, p10.z, acc.z);
        acc.w = fmaf(w.y, p10.w, acc.w);

        acc.x = fmaf(w.z, p01.x, acc.x);
        acc.y = fmaf(w.z, p01.y, acc.y);
        acc.z = fmaf(w.z, p01.z, acc.z);
        acc.w = fmaf(w.z, p01.w, acc.w);

        acc.x = fmaf(w.w, p11.x, acc.x);
        acc.y = fmaf(w.w, p11.y, acc.y);
        acc.z = fmaf(w.w, p11.z, acc.z);
        acc.w = fmaf(w.w, p11.w, acc.w);
    }

    float4 r;
    r.x = acc0.x + acc1.x;
    r.y = acc0.y + acc1.y;
    r.z = acc0.z + acc1.z;
    r.w = acc0.w + acc1.w;

    ((float4*)out)[(size_t)t * 8 + c4] = r;
}

extern "C" void kernel_launch(void* const* d_in, const int* in_sizes, int n_in,
                              void* d_out, int out_size)
{
    const float* value = (const float*)d_in[0];
    const float* loc   = (const float*)d_in[1];
    const float* aw    = (const float*)d_in[2];
    float* out = (float*)d_out;

    cudaFuncSetAttribute(msda_kernel,
                         cudaFuncAttributeMaxDynamicSharedMemorySize,
                         SMEM_BYTES);
    msda_kernel<<<NBLOCKS, THREADS, SMEM_BYTES>>>(value, loc, aw, out);
}

// round 17
// speedup vs baseline: 1.7424x; 1.7424x over previous
#include <cuda_runtime.h>
#include <cstdint>

// MultiScaleDeformableAttention — warp-per-tuple scalar gather (1 line per
// LDG) + smem-staged setup + register pipeline.
//
// value:              (8, 22223, 8, 32)  float32
// sampling_locations: (8, 900, 8, 4, 4, 2) float32
// attention_weights:  (8, 900, 8, 4, 4) float32
// out:                (8, 900, 256) float32
//
// Load-shape rationale: a tuple's corner vector is exactly one 128B line.
// warp-per-tuple with lane=channel makes every corner load a single-line
// LDG.32 (1 L1tex wavefront @ ~1.0 cyc) instead of the 4-line LDG.128
// (4 wavefronts @ ~2.07 cyc replay rate) of the 8-lane layout — halving
// the L1tex serialization that bounds the 37us plateau.
//
// Block = 8 tuples. Phase A: 128 threads compute all 8x16 bilinear setups
// once into smem (kills the 32x redundant ALU of the naive warp layout).
// Phase B: warp w serves tuple w; 16 points through a 3-slot rotating
// register pipeline (scalar slots -> cheap), loads for p+2 issued while
// consuming p.

#define NQ 900
#define NH 8
#define ND 32
#define BS 8
#define NKEYS 22223
#define NTUP (BS * NQ * NH)        // 57600
#define TUPB 8                     // tuples (warps) per block
#define VSTRIDE (NH * ND)          // 256 floats per key

__device__ __forceinline__ void point_setup(
    float lx, float ly, float w,
    int H, int W, int S,
    int& o00, int& o10, int& o01, int& o11,
    float& w00, float& w10, float& w01, float& w11)
{
    const float x = lx * (float)W - 0.5f;
    const float y = ly * (float)H - 0.5f;
    const float x0f = floorf(x);
    const float y0f = floorf(y);
    const int x0 = (int)x0f;
    const int y0 = (int)y0f;
    const int x1 = x0 + 1;
    const int y1 = y0 + 1;
    const float fx1 = x - x0f;
    const float fy1 = y - y0f;
    const float fx0 = 1.0f - fx1;
    const float fy0 = 1.0f - fy1;

    // zero weight factor for OOB corners; fold aw into the y factors.
    const float mx0 = (x0 >= 0 && x0 < W) ? fx0 : 0.0f;
    const float mx1 = (x1 >= 0 && x1 < W) ? fx1 : 0.0f;
    const float my0 = (y0 >= 0 && y0 < H) ? fy0 * w : 0.0f;
    const float my1 = (y1 >= 0 && y1 < H) ? fy1 * w : 0.0f;

    const int cx0 = min(max(x0, 0), W - 1);
    const int cx1 = min(max(x1, 0), W - 1);
    const int cy0 = min(max(y0, 0), H - 1);
    const int cy1 = min(max(y1, 0), H - 1);

    const int r0 = S + cy0 * W;
    const int r1 = S + cy1 * W;

    o00 = (r0 + cx0) * VSTRIDE;
    o10 = (r0 + cx1) * VSTRIDE;
    o01 = (r1 + cx0) * VSTRIDE;
    o11 = (r1 + cx1) * VSTRIDE;

    w00 = mx0 * my0;
    w10 = mx1 * my0;
    w01 = mx0 * my1;
    w11 = mx1 * my1;
}

__global__ __launch_bounds__(256, 5)   // ~51 regs: pipeline fits, occ 62%
void msda_kernel(const float* __restrict__ value,
                 const float* __restrict__ loc,
                 const float* __restrict__ aw,
                 float* __restrict__ out)
{
    __shared__ int4   s_off[TUPB][16];   // [tuple][point] corner offsets
    __shared__ float4 s_wt [TUPB][16];   // [tuple][point] folded weights

    const int tid = threadIdx.x;
    const int t0  = blockIdx.x * TUPB;

    // ---------------- Phase A: setup once per (tuple, point) ----------------
    if (tid < TUPB * 16) {
        const int tl = tid >> 4;            // tuple local 0..7
        const int pi = tid & 15;            // point 0..15
        const int t  = t0 + tl;
        const int l  = pi >> 2;

        const int H = (l == 0) ? 100 : (l == 1) ? 50 : (l == 2) ? 25 : 13;
        const int W = (l == 0) ? 167 : (l == 1) ? 84 : (l == 2) ? 42 : 21;
        const int S = (l == 0) ? 0 : (l == 1) ? 16700 : (l == 2) ? 20900 : 21950;

        const float2 lxy = __ldg((const float2*)(loc + (size_t)t * 32) + pi);
        const float  w   = __ldg(aw + (size_t)t * 16 + pi);

        int   o00, o10, o01, o11;
        float w00, w10, w01, w11;
        point_setup(lxy.x, lxy.y, w, H, W, S,
                    o00, o10, o01, o11, w00, w10, w01, w11);
        s_off[tl][pi] = make_int4(o00, o10, o01, o11);
        s_wt [tl][pi] = make_float4(w00, w10, w01, w11);
    }
    __syncthreads();

    // ---------------- Phase B: warp per tuple, scalar gathers ----------------
    const int wid  = tid >> 5;            // tuple local = warp id
    const int lane = tid & 31;            // channel
    const int t    = t0 + wid;

    const int h = t & 7;
    const int b = (t >> 3) / NQ;

    const float* __restrict__ vbase =
        value + (size_t)b * (NKEYS * NH * ND) + h * ND + lane;

    // 3-slot rotating pipeline; slots hold 4 scalars + 4 weights (8 regs)
    float  v00[3], v10[3], v01[3], v11[3];
    float4 wt[3];

    auto issue = [&](int pi, int s) {
        const int4 o = s_off[wid][pi];     // broadcast LDS.128
        wt[s]        = s_wt [wid][pi];     // broadcast LDS.128
        v00[s] = __ldg(vbase + o.x);       // each: one 128B line warp-wide
        v10[s] = __ldg(vbase + o.y);
        v01[s] = __ldg(vbase + o.z);
        v11[s] = __ldg(vbase + o.w);
    };

    issue(0, 0);
    issue(1, 1);

    float acc0 = 0.0f, acc1 = 0.0f;

    #pragma unroll
    for (int pi = 0; pi < 16; ++pi) {
        const int cur = pi % 3;
        if (pi < 14)
            issue(pi + 2, (pi + 2) % 3);

        const float4 w = wt[cur];
        float& acc = (pi & 1) ? acc1 : acc0;
        acc = fmaf(w.x, v00[cur], acc);
        acc = fmaf(w.y, v10[cur], acc);
        acc = fmaf(w.z, v01[cur], acc);
        acc = fmaf(w.w, v11[cur], acc);
    }

    // out: (b, q, h*32 + lane) == tuple-major scalar: out[t*32 + lane]
    out[(size_t)t * 32 + lane] = acc0 + acc1;
}

extern "C" void kernel_launch(void* const* d_in, const int* in_sizes, int n_in,
                              void* d_out, int out_size)
{
    const float* value = (const float*)d_in[0];
    const float* loc   = (const float*)d_in[1];
    const float* aw    = (const float*)d_in[2];
    float* out = (float*)d_out;

    const int threads = 256;               // 8 warps = 8 tuples per block
    const int blocks  = NTUP / TUPB;       // 7200 (exact)
    msda_kernel<<<blocks, threads>>>(value, loc, aw, out);
}